// round 13
// baseline (speedup 1.0000x reference)
#include <cuda_runtime.h>
#include <float.h>

// fm [B=4, C=256, H=50, W=50] f32, rois [R=300,5] f32 -> out [R,256,7,7] f32.
#define PH 7
#define PW 7
#define B_ 4
#define C_ 256
#define H_ 50
#define W_ 50
#define HW (H_ * W_)
#define C4 (C_ / 4)                    // row length in float4 units
#define R_MAX 512
#define GRID_POOL 1184                 // 148 SMs x 8 resident blocks

// channels-last scratch: fmT[b][y][x][c]  (10.24 MB)
__device__ float g_fmT[B_ * HW * C_];

__device__ int    g_pix[R_MAX];        // b * HW  (pixel-row base)
__device__ uchar2 g_hh[R_MAX][PH];     // {abs row start, strip height}
__device__ uchar2 g_ww[R_MAX][PW];     // {abs col start, bin width}

__device__ __forceinline__ int clampi(int v, int lo, int hi) {
    return min(max(v, lo), hi);
}

// ROI box + bin-edge math for one roi (jnp.round == rintf under RN).
__device__ __forceinline__ void prep_one_roi(const float* __restrict__ rois,
                                             int r) {
    const float* p = rois + r * 5;
    int b  = (int)p[4];                               // float truncation
    int x0 = clampi((int)rintf(p[0]), 0, W_ - 1);
    int x1 = clampi((int)rintf(p[2]), 0, W_ - 1);
    int y0 = clampi((int)rintf(p[1]), 0, H_ - 1);
    int y1 = clampi((int)rintf(p[3]), 0, H_ - 1);
    x1 = max(x1, x0 + 1);   // edges may reach 50; reads stay <= 49
    y1 = max(y1, y0 + 1);
    int w = x1 - x0, h = y1 - y0;

    g_pix[r] = b * HW;
    #pragma unroll
    for (int i = 0; i < PH; ++i) {
        int s = y0 + (i * h) / PH;
        int e = y0 + ((i + 1) * h + PH - 1) / PH;     // ceil
        g_hh[r][i] = make_uchar2((unsigned char)s, (unsigned char)(e - s));
    }
    #pragma unroll
    for (int i = 0; i < PW; ++i) {
        int s = x0 + (i * w) / PW;
        int e = x0 + ((i + 1) * w + PW - 1) / PW;
        g_ww[r][i] = make_uchar2((unsigned char)s, (unsigned char)(e - s));
    }
}

// [256, 2500] -> [2500, 256] transpose per batch, 32c x 64hw tiles.
// Block (0,0,0) additionally computes the per-ROI tables (runs in the
// shadow of the other transpose blocks; no extra launch).
__global__ __launch_bounds__(256) void transpose_kernel(
        const float* __restrict__ in, const float* __restrict__ rois, int R) {
    __shared__ float tile[32][65];
    const int b   = blockIdx.z;
    const int hw0 = blockIdx.x * 64;
    const int c0  = blockIdx.y * 32;
    const int tx  = threadIdx.x;          // 32
    const int ty  = threadIdx.y;          // 8
    const int tid = ty * 32 + tx;

    if (blockIdx.x == 0 && blockIdx.y == 0 && blockIdx.z == 0) {
        for (int r = tid; r < R; r += 256)
            prep_one_roi(rois, r);
    }

    #pragma unroll
    for (int j = 0; j < 4; ++j) {
        const int cl = ty + j * 8;
        const float* src = in + (size_t)(b * C_ + c0 + cl) * HW;
        int hw = hw0 + tx;
        if (hw < HW)      tile[cl][tx]      = src[hw];
        hw = hw0 + 32 + tx;
        if (hw < HW)      tile[cl][tx + 32] = src[hw];
    }
    __syncthreads();
    #pragma unroll
    for (int j = 0; j < 8; ++j) {
        const int hwl = ty + j * 8;
        const int hw  = hw0 + hwl;
        if (hw < HW)
            g_fmT[(size_t)(b * HW + hw) * C_ + c0 + tx] = tile[tx][hwl];
    }
}

// Persistent single-wave pool: 1184 blocks x 224 threads loop over items
// (half, r, ph). Warp = pw bin, lane = float4 quad (128 consecutive
// channels = 512B dense warp-load). Double-buffered smem staging,
// direct NCHW stores (7-float runs).
__global__ __launch_bounds__(224) void roi_pool_kernel(
        float* __restrict__ out, int nitems, int R) {
    __shared__ float so[2][128 * PW];      // double buffer, 7 KB total

    const int lane = threadIdx.x & 31;
    const int pw   = threadIdx.x >> 5;     // 0..6
    const float4* f4 = (const float4*)g_fmT;

    int buf = 0;
    for (int item = blockIdx.x; item < nitems; item += GRID_POOL, buf ^= 1) {
        const int ph   = item % PH;
        const int t    = item / PH;        // = half * R + r
        const int r    = t % R;
        const int half = t / R;

        const uchar2 hi = g_hh[r][ph];
        const uchar2 wi = g_ww[r][pw];
        const int hs = hi.x, sh = hi.y;    // 1..8 rows
        const int ws = wi.x, bw = wi.y;    // 1..8 cols

        const float4* base =
            f4 + ((size_t)g_pix[r] + hs * W_ + ws) * C4 + half * 32 + lane;

        float4 acc = make_float4(-FLT_MAX, -FLT_MAX, -FLT_MAX, -FLT_MAX);
        for (int y = 0; y < sh; ++y) {
            const float4* rowp = base + (size_t)(y * W_) * C4;
            #pragma unroll 4
            for (int x = 0; x < bw; ++x) {
                float4 a = __ldg(rowp + (size_t)x * C4);
                acc.x = fmaxf(acc.x, a.x);
                acc.y = fmaxf(acc.y, a.y);
                acc.z = fmaxf(acc.z, a.z);
                acc.w = fmaxf(acc.w, a.w);
            }
        }

        float* sb = so[buf];
        sb[(4 * lane + 0) * PW + pw] = acc.x;
        sb[(4 * lane + 1) * PW + pw] = acc.y;
        sb[(4 * lane + 2) * PW + pw] = acc.z;
        sb[(4 * lane + 3) * PW + pw] = acc.w;
        __syncthreads();

        // out[r][half*128 + c_local][ph][pw]; 896 floats, 4 per thread
        float* ob = out + ((size_t)r * C_ + half * 128) * (PH * PW) + ph * PW;
        #pragma unroll
        for (int i = threadIdx.x; i < 128 * PW; i += 224) {
            int c  = i / PW;
            int pp = i - c * PW;
            ob[c * (PH * PW) + pp] = sb[i];
        }
        // no trailing sync: the buffer written next iteration is reused
        // only two items later, after the intervening __syncthreads.
    }
}

extern "C" void kernel_launch(void* const* d_in, const int* in_sizes, int n_in,
                              void* d_out, int out_size) {
    const float* fm   = (const float*)d_in[0];
    const float* rois = (const float*)d_in[1];
    float* out = (float*)d_out;

    int R = in_sizes[1] / 5;               // 300

    dim3 tgrid((HW + 63) / 64, C_ / 32, B_);   // 40 x 8 x 4
    transpose_kernel<<<tgrid, dim3(32, 8)>>>(fm, rois, R);

    int nitems = 2 * R * PH;               // 4200
    roi_pool_kernel<<<GRID_POOL, 224>>>(out, nitems, R);
}

// round 14
// speedup vs baseline: 1.2384x; 1.2384x over previous
#include <cuda_runtime.h>
#include <float.h>

// fm [B=4, C=256, H=50, W=50] f32, rois [R=300,5] f32 -> out [R,256,7,7] f32.
#define PH 7
#define PW 7
#define B_ 4
#define C_ 256
#define H_ 50
#define W_ 50
#define HW (H_ * W_)
#define C4 (C_ / 4)                    // row length in float4 units

// channels-last scratch: fmT[b][y][x][c]  (10.24 MB)
__device__ float g_fmT[B_ * HW * C_];

__device__ __forceinline__ int clampi(int v, int lo, int hi) {
    return min(max(v, lo), hi);
}

// [256, 2500] -> [2500, 256] transpose per batch, 32c x 64hw tiles. (validated)
__global__ __launch_bounds__(256) void transpose_kernel(
        const float* __restrict__ in) {
    __shared__ float tile[32][65];
    const int b   = blockIdx.z;
    const int hw0 = blockIdx.x * 64;
    const int c0  = blockIdx.y * 32;
    const int tx  = threadIdx.x;          // 32
    const int ty  = threadIdx.y;          // 8

    #pragma unroll
    for (int j = 0; j < 4; ++j) {
        const int cl = ty + j * 8;
        const float* src = in + (size_t)(b * C_ + c0 + cl) * HW;
        int hw = hw0 + tx;
        if (hw < HW)      tile[cl][tx]      = src[hw];
        hw = hw0 + 32 + tx;
        if (hw < HW)      tile[cl][tx + 32] = src[hw];
    }
    __syncthreads();
    #pragma unroll
    for (int j = 0; j < 8; ++j) {
        const int hwl = ty + j * 8;
        const int hw  = hw0 + hwl;
        if (hw < HW)
            g_fmT[(size_t)(b * HW + hw) * C_ + c0 + tx] = tile[tx][hwl];
    }
}

__device__ __forceinline__ void fold4(float4& acc, float4 a) {
    acc.x = fmaxf(acc.x, a.x);
    acc.y = fmaxf(acc.y, a.y);
    acc.z = fmaxf(acc.z, a.z);
    acc.w = fmaxf(acc.w, a.w);
}

// Branch-free bin max: NC unrolled column loads per row with clamped
// duplicate offsets (duplicates are no-ops for max and hit L1).
template <int NC>
__device__ __forceinline__ float4 pool_bin(const float4* base, int sh, int bw) {
    int off[NC];
    #pragma unroll
    for (int j = 0; j < NC; ++j)
        off[j] = min(j, bw - 1) * C4;
    float4 acc = make_float4(-FLT_MAX, -FLT_MAX, -FLT_MAX, -FLT_MAX);
    for (int y = 0; y < sh; ++y, base += W_ * C4) {
        #pragma unroll
        for (int j = 0; j < NC; ++j) {
            float4 a = __ldg(base + off[j]);
            fold4(acc, a);
        }
    }
    return acc;
}

// Block = (ph, roi, 128-channel half). Warp = pw bin, lane = float4 quad
// (warp-load = 128 consecutive channels = 512B dense). Inner loop is a
// fully unrolled clamped-offset class (no branches, MLP = NC).
__global__ __launch_bounds__(224) void roi_pool_kernel(
        const float* __restrict__ rois, float* __restrict__ out) {
    __shared__ float so[128 * PW];         // [c_local*7 + pw], 3.5 KB

    const int ph   = blockIdx.x;
    const int r    = blockIdx.y;
    const int half = blockIdx.z;           // 0..1 (128 channels each)
    const int lane = threadIdx.x & 31;
    const int pw   = threadIdx.x >> 5;     // 0..6

    // ---- ROI box (block-uniform; jnp.round == rintf under RN) ----
    const float* rp = rois + r * 5;
    const int b  = (int)__ldg(rp + 4);                 // float truncation
    int x0 = clampi((int)rintf(__ldg(rp + 0)), 0, W_ - 1);
    int x1 = clampi((int)rintf(__ldg(rp + 2)), 0, W_ - 1);
    int y0 = clampi((int)rintf(__ldg(rp + 1)), 0, H_ - 1);
    int y1 = clampi((int)rintf(__ldg(rp + 3)), 0, H_ - 1);
    x1 = max(x1, x0 + 1);                  // edges may reach 50; reads <= 49
    y1 = max(y1, y0 + 1);
    const int w = x1 - x0;                 // 1..49
    const int h = y1 - y0;

    const int hs = y0 + (ph * h) / PH;
    const int sh = y0 + ((ph + 1) * h + PH - 1) / PH - hs;   // 1..8
    const int ws = x0 + (pw * w) / PW;
    const int bw = x0 + ((pw + 1) * w + PW - 1) / PW - ws;   // 1..8

    const float4* base = (const float4*)g_fmT
        + ((size_t)b * HW + hs * W_ + ws) * C4 + half * 32 + lane;

    float4 acc;
    if (bw == 1)      acc = pool_bin<1>(base, sh, bw);
    else if (bw == 2) acc = pool_bin<2>(base, sh, bw);
    else if (bw <= 4) acc = pool_bin<4>(base, sh, bw);
    else              acc = pool_bin<8>(base, sh, bw);

    so[(4 * lane + 0) * PW + pw] = acc.x;
    so[(4 * lane + 1) * PW + pw] = acc.y;
    so[(4 * lane + 2) * PW + pw] = acc.z;
    so[(4 * lane + 3) * PW + pw] = acc.w;
    __syncthreads();

    // out[r][half*128 + c_local][ph][pw]; 896 floats, 4 per thread
    float* ob = out + ((size_t)r * C_ + half * 128) * (PH * PW) + ph * PW;
    #pragma unroll
    for (int i = threadIdx.x; i < 128 * PW; i += 224) {
        int c  = i / PW;
        int pp = i - c * PW;
        ob[c * (PH * PW) + pp] = so[i];
    }
}

extern "C" void kernel_launch(void* const* d_in, const int* in_sizes, int n_in,
                              void* d_out, int out_size) {
    const float* fm   = (const float*)d_in[0];
    const float* rois = (const float*)d_in[1];
    float* out = (float*)d_out;

    int R = in_sizes[1] / 5;               // 300

    dim3 tgrid((HW + 63) / 64, C_ / 32, B_);   // 40 x 8 x 4
    transpose_kernel<<<tgrid, dim3(32, 8)>>>(fm);

    dim3 pgrid(PH, R, 2);                  // 7 x 300 x 2
    roi_pool_kernel<<<pgrid, 224>>>(rois, out);
}